// round 1
// baseline (speedup 1.0000x reference)
#include <cuda_runtime.h>

#define EPS 1e-6f

// Problem shape (fixed by the dataset)
constexpr int NBATCH = 4;
constexpr int L      = 4096;
constexpr int H      = 12;
constexpr int D      = 64;
constexpr int M      = 64;
constexpr int T      = 128;           // chunk length
constexpr int NC     = L / T;         // 32 chunks
constexpr int NH     = NBATCH * H;    // 48 (n,h) pairs
constexpr int STATE  = D * M + D;     // 4160 floats per (n,h,chunk): KV + ksum

// Scratch for per-chunk states (static __device__ allocation — no cudaMalloc)
__device__ float g_state[(size_t)NH * NC * STATE];

__device__ __forceinline__ float phi(float x) {
    // elu(x) + 1  ==  x > 0 ? x + 1 : exp(x)
    return x > 0.0f ? x + 1.0f : __expf(x);
}

// ---------------------------------------------------------------------------
// Kernel 1: per-chunk sums  KV[d][m] = sum_t phi(k)[t][d] * v[t][m],
//           ksum[d] = sum_t phi(k)[t][d]
// ---------------------------------------------------------------------------
constexpr int SMEM1 = 2 * T * D * 4;  // 64 KB

__global__ __launch_bounds__(256)
void k_chunksum(const float* __restrict__ kin, const float* __restrict__ vin) {
    extern __shared__ float sm[];
    float* sk = sm;            // [T][D]
    float* sv = sm + T * D;    // [T][D]

    const int c  = blockIdx.x;
    const int nh = blockIdx.y;
    const int n  = nh / H, h = nh % H;
    const int l0 = c * T;
    const int tid = threadIdx.x;

    for (int e = tid; e < T * (D / 4); e += 256) {
        int row = e >> 4;
        int c4  = (e & 15) * 4;
        size_t g = ((size_t)(n * L + l0 + row) * H + h) * D + c4;
        float4 kv = *(const float4*)(kin + g);
        kv.x = phi(kv.x); kv.y = phi(kv.y); kv.z = phi(kv.z); kv.w = phi(kv.w);
        *(float4*)(sk + row * D + c4) = kv;
        *(float4*)(sv + row * D + c4) = *(const float4*)(vin + g);
    }
    __syncthreads();

    const int d0 = (tid >> 4) * 4;
    const int m0 = (tid & 15) * 4;
    float acc[4][4];
    #pragma unroll
    for (int r = 0; r < 4; r++)
        acc[r][0] = acc[r][1] = acc[r][2] = acc[r][3] = 0.0f;

    for (int t = 0; t < T; t++) {
        float4 a = *(float4*)(sk + t * D + d0);
        float4 b = *(float4*)(sv + t * D + m0);
        float ar[4] = {a.x, a.y, a.z, a.w};
        #pragma unroll
        for (int r = 0; r < 4; r++) {
            acc[r][0] += ar[r] * b.x;
            acc[r][1] += ar[r] * b.y;
            acc[r][2] += ar[r] * b.z;
            acc[r][3] += ar[r] * b.w;
        }
    }

    float* outp = g_state + ((size_t)nh * NC + c) * STATE;
    #pragma unroll
    for (int r = 0; r < 4; r++)
        *(float4*)(outp + (d0 + r) * M + m0) =
            make_float4(acc[r][0], acc[r][1], acc[r][2], acc[r][3]);

    if (tid < D) {
        float s = 0.0f;
        for (int t = 0; t < T; t++) s += sk[t * D + tid];
        outp[D * M + tid] = s;
    }
}

// ---------------------------------------------------------------------------
// Kernel 2: in-place exclusive prefix scan over chunks, per (n,h)
// ---------------------------------------------------------------------------
__global__ __launch_bounds__(256)
void k_scan() {
    const int nh = blockIdx.x;
    for (int e = threadIdx.x; e < STATE; e += 256) {
        float acc = 0.0f;
        size_t base = (size_t)nh * NC * STATE + e;
        for (int c = 0; c < NC; c++) {
            float t = g_state[base + (size_t)c * STATE];
            g_state[base + (size_t)c * STATE] = acc;
            acc += t;
        }
    }
}

// ---------------------------------------------------------------------------
// Kernel 3: per-chunk output
//   o = phi(q) @ S_prefix + tril(phi(q) phi(k)^T) @ v
//   z = phi(q).ksum_prefix + rowsum(tril(A)) + eps ;  out = o / z
// ---------------------------------------------------------------------------
constexpr int QS = 68;    // sq row stride (pad: avoid bank conflicts on column reads)
constexpr int TS = 132;   // k-transposed row stride (mult of 4 for float4 alignment)
constexpr int AS = 132;   // sA row stride

constexpr int OFF_SQ = 0;                  // [T][QS]
constexpr int OFF_KT = OFF_SQ + T * QS;    // [D][TS]  (phi(k) transposed)
constexpr int OFF_SV = OFF_KT + D * TS;    // [T][M]
constexpr int OFF_SA = OFF_SV + T * M;     // [T][AS]
constexpr int OFF_SS = OFF_SA + T * AS;    // [D][M]   (prefix KV state)
constexpr int OFF_KS = OFF_SS + D * M;     // [D]      (prefix ksum)
constexpr int SMEM3  = (OFF_KS + D) * 4;   // 185600 B

__global__ __launch_bounds__(256, 1)
void k_output(const float* __restrict__ qin, const float* __restrict__ kin,
              const float* __restrict__ vin, float* __restrict__ out) {
    extern __shared__ float sm[];
    float* sq  = sm + OFF_SQ;
    float* kt  = sm + OFF_KT;
    float* sv  = sm + OFF_SV;
    float* sA  = sm + OFF_SA;
    float* sS  = sm + OFF_SS;
    float* sks = sm + OFF_KS;

    const int c  = blockIdx.x;
    const int nh = blockIdx.y;
    const int n  = nh / H, h = nh % H;
    const int l0 = c * T;
    const int tid = threadIdx.x;

    // ---- load q (phi), k (phi, transposed), v
    for (int e = tid; e < T * (D / 4); e += 256) {
        int row = e >> 4;
        int c4  = (e & 15) * 4;
        size_t g = ((size_t)(n * L + l0 + row) * H + h) * D + c4;
        float4 qv = *(const float4*)(qin + g);
        qv.x = phi(qv.x); qv.y = phi(qv.y); qv.z = phi(qv.z); qv.w = phi(qv.w);
        *(float4*)(sq + row * QS + c4) = qv;
        float4 kv = *(const float4*)(kin + g);
        kt[(c4 + 0) * TS + row] = phi(kv.x);
        kt[(c4 + 1) * TS + row] = phi(kv.y);
        kt[(c4 + 2) * TS + row] = phi(kv.z);
        kt[(c4 + 3) * TS + row] = phi(kv.w);
        *(float4*)(sv + row * M + c4) = *(const float4*)(vin + g);
    }
    // ---- load exclusive-prefix state
    {
        const float* st = g_state + ((size_t)nh * NC + c) * STATE;
        for (int e = tid; e < STATE / 4; e += 256) {
            float4 s4 = *(const float4*)(st + e * 4);
            int idx = e * 4;
            if (idx < D * M) {
                *(float4*)(sS + idx) = s4;
            } else {
                int d0 = idx - D * M;
                sks[d0] = s4.x; sks[d0 + 1] = s4.y;
                sks[d0 + 2] = s4.z; sks[d0 + 3] = s4.w;
            }
        }
    }
    __syncthreads();

    const int rowg = tid >> 4, colg = tid & 15;
    const int i0 = rowg * 8, j0 = colg * 8;

    // ---- phase B: A = tril(phi(q) @ phi(k)^T), 8x8 register tile per thread
    float a8[8][8];
    #pragma unroll
    for (int r = 0; r < 8; r++)
        #pragma unroll
        for (int j = 0; j < 8; j++) a8[r][j] = 0.0f;

    if (j0 <= i0 + 7) {   // tile touches the lower triangle
        for (int d = 0; d < D; d++) {
            float4 b0 = *(float4*)(kt + d * TS + j0);
            float4 b1 = *(float4*)(kt + d * TS + j0 + 4);
            float bb[8] = {b0.x, b0.y, b0.z, b0.w, b1.x, b1.y, b1.z, b1.w};
            #pragma unroll
            for (int r = 0; r < 8; r++) {
                float av = sq[(i0 + r) * QS + d];
                #pragma unroll
                for (int j = 0; j < 8; j++) a8[r][j] += av * bb[j];
            }
        }
    }
    #pragma unroll
    for (int r = 0; r < 8; r++) {
        int i = i0 + r;
        #pragma unroll
        for (int j = 0; j < 8; j++)
            if (j0 + j > i) a8[r][j] = 0.0f;   // causal mask (inclusive diagonal)
        *(float4*)(sA + i * AS + j0)     = make_float4(a8[r][0], a8[r][1], a8[r][2], a8[r][3]);
        *(float4*)(sA + i * AS + j0 + 4) = make_float4(a8[r][4], a8[r][5], a8[r][6], a8[r][7]);
    }
    __syncthreads();

    // ---- phase AC: o = q@S + A@v ; z = q.ksum + rowsum(A) + eps
    const int m0 = colg * 4;
    float acc[8][4];
    float zac[8];
    #pragma unroll
    for (int r = 0; r < 8; r++) {
        zac[r] = EPS;
        acc[r][0] = acc[r][1] = acc[r][2] = acc[r][3] = 0.0f;
    }

    for (int d = 0; d < D; d++) {
        float4 s4 = *(float4*)(sS + d * M + m0);
        float kd = sks[d];
        #pragma unroll
        for (int r = 0; r < 8; r++) {
            float av = sq[(i0 + r) * QS + d];
            acc[r][0] += av * s4.x; acc[r][1] += av * s4.y;
            acc[r][2] += av * s4.z; acc[r][3] += av * s4.w;
            zac[r]    += av * kd;
        }
    }
    const int jmax = i0 + 8;   // rows i0..i0+7 only need keys j <= i0+7
    for (int j = 0; j < jmax; j++) {
        float4 v4 = *(float4*)(sv + j * M + m0);
        #pragma unroll
        for (int r = 0; r < 8; r++) {
            float av = sA[(i0 + r) * AS + j];   // zero above diagonal
            acc[r][0] += av * v4.x; acc[r][1] += av * v4.y;
            acc[r][2] += av * v4.z; acc[r][3] += av * v4.w;
            zac[r]    += av;
        }
    }
    #pragma unroll
    for (int r = 0; r < 8; r++) {
        float inv = 1.0f / zac[r];
        size_t g = ((size_t)(n * L + l0 + i0 + r) * H + h) * M + m0;
        *(float4*)(out + g) = make_float4(acc[r][0] * inv, acc[r][1] * inv,
                                          acc[r][2] * inv, acc[r][3] * inv);
    }
}

// ---------------------------------------------------------------------------
extern "C" void kernel_launch(void* const* d_in, const int* in_sizes, int n_in,
                              void* d_out, int out_size) {
    const float* q = (const float*)d_in[0];
    const float* k = (const float*)d_in[1];
    const float* v = (const float*)d_in[2];
    float* out = (float*)d_out;

    cudaFuncSetAttribute(k_chunksum, cudaFuncAttributeMaxDynamicSharedMemorySize, SMEM1);
    cudaFuncSetAttribute(k_output,   cudaFuncAttributeMaxDynamicSharedMemorySize, SMEM3);

    dim3 grid(NC, NH);
    k_chunksum<<<grid, 256, SMEM1>>>(k, v);
    k_scan<<<NH, 256>>>();
    k_output<<<grid, 256, SMEM3>>>(q, k, v, out);
}

// round 5
// speedup vs baseline: 1.1793x; 1.1793x over previous
#include <cuda_runtime.h>

#define EPS 1e-6f

// Problem shape (fixed by the dataset)
constexpr int NBATCH = 4;
constexpr int L      = 4096;
constexpr int H      = 12;
constexpr int D      = 64;
constexpr int M      = 64;
constexpr int T      = 64;            // chunk length
constexpr int NC     = L / T;         // 64 chunks
constexpr int NH     = NBATCH * H;    // 48 (n,h) pairs
constexpr int STATE  = D * M + D;     // 4160 floats per (n,h,chunk): KV + ksum

// Scratch for per-chunk states (static __device__ allocation — no cudaMalloc)
__device__ float g_state[(size_t)NH * NC * STATE];

__device__ __forceinline__ float phi(float x) {
    // elu(x) + 1  ==  x > 0 ? x + 1 : exp(x)
    return x > 0.0f ? x + 1.0f : __expf(x);
}

// ---------------------------------------------------------------------------
// Kernel 1: per-chunk sums  KV[d][m] = sum_t phi(k)[t][d] * v[t][m],
//           ksum[d] = sum_t phi(k)[t][d]
// ---------------------------------------------------------------------------
constexpr int SMEM1 = 2 * T * D * 4;  // 32 KB

__global__ __launch_bounds__(256)
void k_chunksum(const float* __restrict__ kin, const float* __restrict__ vin) {
    extern __shared__ float sm[];
    float* sk = sm;            // [T][D]
    float* sv = sm + T * D;    // [T][D]

    const int c  = blockIdx.x;
    const int nh = blockIdx.y;
    const int n  = nh / H, h = nh % H;
    const int l0 = c * T;
    const int tid = threadIdx.x;

    for (int e = tid; e < T * (D / 4); e += 256) {
        int row = e >> 4;
        int c4  = (e & 15) * 4;
        size_t g = ((size_t)(n * L + l0 + row) * H + h) * D + c4;
        float4 kv = *(const float4*)(kin + g);
        kv.x = phi(kv.x); kv.y = phi(kv.y); kv.z = phi(kv.z); kv.w = phi(kv.w);
        *(float4*)(sk + row * D + c4) = kv;
        *(float4*)(sv + row * D + c4) = *(const float4*)(vin + g);
    }
    __syncthreads();

    const int d0 = (tid >> 4) * 4;
    const int m0 = (tid & 15) * 4;
    float acc[4][4];
    #pragma unroll
    for (int r = 0; r < 4; r++)
        acc[r][0] = acc[r][1] = acc[r][2] = acc[r][3] = 0.0f;

    #pragma unroll 4
    for (int t = 0; t < T; t++) {
        float4 a = *(float4*)(sk + t * D + d0);
        float4 b = *(float4*)(sv + t * D + m0);
        float ar[4] = {a.x, a.y, a.z, a.w};
        #pragma unroll
        for (int r = 0; r < 4; r++) {
            acc[r][0] += ar[r] * b.x;
            acc[r][1] += ar[r] * b.y;
            acc[r][2] += ar[r] * b.z;
            acc[r][3] += ar[r] * b.w;
        }
    }

    float* outp = g_state + ((size_t)nh * NC + c) * STATE;
    #pragma unroll
    for (int r = 0; r < 4; r++)
        *(float4*)(outp + (d0 + r) * M + m0) =
            make_float4(acc[r][0], acc[r][1], acc[r][2], acc[r][3]);

    if (tid < D) {
        float s = 0.0f;
        #pragma unroll 4
        for (int t = 0; t < T; t++) s += sk[t * D + tid];
        outp[D * M + tid] = s;
    }
}

// ---------------------------------------------------------------------------
// Kernel 2: in-place exclusive prefix scan over chunks, per (n,h).
// Parallelized over 8 segments of the state vector -> 384 blocks.
// ---------------------------------------------------------------------------
constexpr int SCAN_SEG = 8;
constexpr int SEG_LEN  = STATE / SCAN_SEG;   // 520

__global__ __launch_bounds__(256)
void k_scan() {
    const int nh  = blockIdx.x;
    const int seg = blockIdx.y;
    const int e0  = seg * SEG_LEN;
    for (int e = e0 + threadIdx.x; e < e0 + SEG_LEN; e += 256) {
        float acc = 0.0f;
        size_t base = (size_t)nh * NC * STATE + e;
        #pragma unroll 4
        for (int c = 0; c < NC; c++) {
            float t = g_state[base + (size_t)c * STATE];
            g_state[base + (size_t)c * STATE] = acc;
            acc += t;
        }
    }
}

// ---------------------------------------------------------------------------
// Kernel 3: per-chunk output
//   o = phi(q) @ S_prefix + tril(phi(q) phi(k)^T) @ v
//   z = phi(q).ksum_prefix + rowsum(tril(A)) + eps ;  out = o / z
// T=64: smem ~85KB -> 2 CTAs/SM -> 16 warps resident.
// ---------------------------------------------------------------------------
constexpr int QS = 68;    // sq row stride (pad: avoid bank conflicts)
constexpr int TS = 68;    // k-transposed row stride
constexpr int AS = 68;    // sA row stride

constexpr int OFF_SQ = 0;                  // [T][QS]
constexpr int OFF_KT = OFF_SQ + T * QS;    // [D][TS]  (phi(k) transposed)
constexpr int OFF_SV = OFF_KT + D * TS;    // [T][M]
constexpr int OFF_SA = OFF_SV + T * M;     // [T][AS]
constexpr int OFF_SS = OFF_SA + T * AS;    // [D][M]   (prefix KV state)
constexpr int OFF_KS = OFF_SS + D * M;     // [D]      (prefix ksum)
constexpr int SMEM3  = (OFF_KS + D) * 4;   // 85248 B

__global__ __launch_bounds__(256, 2)
void k_output(const float* __restrict__ qin, const float* __restrict__ kin,
              const float* __restrict__ vin, float* __restrict__ out) {
    extern __shared__ float sm[];
    float* sq  = sm + OFF_SQ;
    float* kt  = sm + OFF_KT;
    float* sv  = sm + OFF_SV;
    float* sA  = sm + OFF_SA;
    float* sS  = sm + OFF_SS;
    float* sks = sm + OFF_KS;

    const int c  = blockIdx.x;
    const int nh = blockIdx.y;
    const int n  = nh / H, h = nh % H;
    const int l0 = c * T;
    const int tid = threadIdx.x;

    // ---- load q (phi), k (phi, transposed), v
    for (int e = tid; e < T * (D / 4); e += 256) {
        int row = e >> 4;
        int c4  = (e & 15) * 4;
        size_t g = ((size_t)(n * L + l0 + row) * H + h) * D + c4;
        float4 qv = *(const float4*)(qin + g);
        qv.x = phi(qv.x); qv.y = phi(qv.y); qv.z = phi(qv.z); qv.w = phi(qv.w);
        *(float4*)(sq + row * QS + c4) = qv;
        float4 kv = *(const float4*)(kin + g);
        kt[(c4 + 0) * TS + row] = phi(kv.x);
        kt[(c4 + 1) * TS + row] = phi(kv.y);
        kt[(c4 + 2) * TS + row] = phi(kv.z);
        kt[(c4 + 3) * TS + row] = phi(kv.w);
        *(float4*)(sv + row * M + c4) = *(const float4*)(vin + g);
    }
    // ---- load exclusive-prefix state
    {
        const float* st = g_state + ((size_t)nh * NC + c) * STATE;
        for (int e = tid; e < STATE / 4; e += 256) {
            float4 s4 = *(const float4*)(st + e * 4);
            int idx = e * 4;
            if (idx < D * M) {
                *(float4*)(sS + idx) = s4;
            } else {
                int d0 = idx - D * M;
                sks[d0] = s4.x; sks[d0 + 1] = s4.y;
                sks[d0 + 2] = s4.z; sks[d0 + 3] = s4.w;
            }
        }
    }
    __syncthreads();

    const int rowg = tid >> 4, colg = tid & 15;
    const int i0 = rowg * 4, j0 = colg * 4;

    // ---- phase B: A = tril(phi(q) @ phi(k)^T), 4x4 register tile per thread
    float a4[4][4];
    #pragma unroll
    for (int r = 0; r < 4; r++)
        #pragma unroll
        for (int j = 0; j < 4; j++) a4[r][j] = 0.0f;

    if (j0 <= i0 + 3) {   // tile touches the lower triangle
        #pragma unroll 4
        for (int d = 0; d < D; d++) {
            float4 b = *(float4*)(kt + d * TS + j0);
            float bb[4] = {b.x, b.y, b.z, b.w};
            #pragma unroll
            for (int r = 0; r < 4; r++) {
                float av = sq[(i0 + r) * QS + d];
                #pragma unroll
                for (int j = 0; j < 4; j++) a4[r][j] += av * bb[j];
            }
        }
    }
    #pragma unroll
    for (int r = 0; r < 4; r++) {
        int i = i0 + r;
        #pragma unroll
        for (int j = 0; j < 4; j++)
            if (j0 + j > i) a4[r][j] = 0.0f;   // causal mask (inclusive diagonal)
        *(float4*)(sA + i * AS + j0) = make_float4(a4[r][0], a4[r][1], a4[r][2], a4[r][3]);
    }
    __syncthreads();

    // ---- phase AC: o = q@S + A@v ; z = q.ksum + rowsum(A) + eps
    const int m0 = colg * 4;
    float acc[4][4];
    float zac[4];
    #pragma unroll
    for (int r = 0; r < 4; r++) {
        zac[r] = EPS;
        acc[r][0] = acc[r][1] = acc[r][2] = acc[r][3] = 0.0f;
    }

    #pragma unroll 4
    for (int d = 0; d < D; d++) {
        float4 s4 = *(float4*)(sS + d * M + m0);
        float kd = sks[d];
        #pragma unroll
        for (int r = 0; r < 4; r++) {
            float av = sq[(i0 + r) * QS + d];
            acc[r][0] += av * s4.x; acc[r][1] += av * s4.y;
            acc[r][2] += av * s4.z; acc[r][3] += av * s4.w;
            zac[r]    += av * kd;
        }
    }
    const int jmax = i0 + 4;   // rows i0..i0+3 only need keys j <= i0+3
    #pragma unroll 4
    for (int j = 0; j < jmax; j++) {
        float4 v4 = *(float4*)(sv + j * M + m0);
        #pragma unroll
        for (int r = 0; r < 4; r++) {
            float av = sA[(i0 + r) * AS + j];   // zero above diagonal
            acc[r][0] += av * v4.x; acc[r][1] += av * v4.y;
            acc[r][2] += av * v4.z; acc[r][3] += av * v4.w;
            zac[r]    += av;
        }
    }
    #pragma unroll
    for (int r = 0; r < 4; r++) {
        float inv = 1.0f / zac[r];
        size_t g = ((size_t)(n * L + l0 + i0 + r) * H + h) * M + m0;
        *(float4*)(out + g) = make_float4(acc[r][0] * inv, acc[r][1] * inv,
                                          acc[r][2] * inv, acc[r][3] * inv);
    }
}

// ---------------------------------------------------------------------------
extern "C" void kernel_launch(void* const* d_in, const int* in_sizes, int n_in,
                              void* d_out, int out_size) {
    const float* q = (const float*)d_in[0];
    const float* k = (const float*)d_in[1];
    const float* v = (const float*)d_in[2];
    float* out = (float*)d_out;

    cudaFuncSetAttribute(k_output, cudaFuncAttributeMaxDynamicSharedMemorySize, SMEM3);

    dim3 grid(NC, NH);
    k_chunksum<<<grid, 256, SMEM1>>>(k, v);
    dim3 sgrid(NH, SCAN_SEG);
    k_scan<<<sgrid, 256>>>();
    k_output<<<grid, 256, SMEM3>>>(q, k, v, out);
}

// round 13
// speedup vs baseline: 1.3515x; 1.1461x over previous
#include <cuda_runtime.h>
#include <cstdint>

#define EPS 1e-6f

// Problem shape (fixed by the dataset)
constexpr int NBATCH = 4;
constexpr int L      = 4096;
constexpr int H      = 12;
constexpr int D      = 64;
constexpr int M      = 64;
constexpr int T      = 64;            // chunk length
constexpr int NC     = L / T;         // 64 chunks
constexpr int NH     = NBATCH * H;    // 48 (n,h) pairs
constexpr int STATE  = D * M + D;     // 4160 floats per (n,h,chunk): KV + ksum

// Scratch for per-chunk states (static __device__ allocation — no cudaMalloc)
__device__ float g_state[(size_t)NH * NC * STATE];

__device__ __forceinline__ float phi(float x) {
    // elu(x) + 1  ==  x > 0 ? x + 1 : exp(x)
    return x > 0.0f ? x + 1.0f : __expf(x);
}

__device__ __forceinline__ void cp_async16(uint32_t smem_addr, const void* gptr) {
    asm volatile("cp.async.cg.shared.global [%0], [%1], 16;\n"
                 :: "r"(smem_addr), "l"(gptr));
}

// ---------------------------------------------------------------------------
// Kernel 1: per-chunk sums  KV[d][m] = sum_t phi(k)[t][d] * v[t][m],
//           ksum[d] = sum_t phi(k)[t][d]
// 128 threads, 8x4 register tile per thread: 3 LDS.128 per 32 FMA
// (vs 2 per 16 before) -> LDS crossbar pressure cut by 25%.
// ---------------------------------------------------------------------------
constexpr int SMEM1 = 2 * T * D * 4;  // 32 KB

__global__ __launch_bounds__(128)
void k_chunksum(const float* __restrict__ kin, const float* __restrict__ vin) {
    extern __shared__ float sm[];
    float* sk = sm;            // [T][D]
    float* sv = sm + T * D;    // [T][D]

    const int c  = blockIdx.x;
    const int nh = blockIdx.y;
    const int n  = nh / H, h = nh % H;
    const int l0 = c * T;
    const int tid = threadIdx.x;

    for (int e = tid; e < T * (D / 4); e += 128) {
        int row = e >> 4;
        int c4  = (e & 15) * 4;
        size_t g = ((size_t)(n * L + l0 + row) * H + h) * D + c4;
        float4 kv = *(const float4*)(kin + g);
        kv.x = phi(kv.x); kv.y = phi(kv.y); kv.z = phi(kv.z); kv.w = phi(kv.w);
        *(float4*)(sk + row * D + c4) = kv;
        *(float4*)(sv + row * D + c4) = *(const float4*)(vin + g);
    }
    __syncthreads();

    // 128 threads: 8 row-groups (d, 8-wide) x 16 col-groups (m, 4-wide)
    const int d0 = (tid >> 4) * 8;
    const int m0 = (tid & 15) * 4;
    float acc[8][4];
    #pragma unroll
    for (int r = 0; r < 8; r++)
        acc[r][0] = acc[r][1] = acc[r][2] = acc[r][3] = 0.0f;

    #pragma unroll 4
    for (int t = 0; t < T; t++) {
        float4 a0 = *(float4*)(sk + t * D + d0);
        float4 a1 = *(float4*)(sk + t * D + d0 + 4);
        float4 b  = *(float4*)(sv + t * D + m0);
        float ar[8] = {a0.x, a0.y, a0.z, a0.w, a1.x, a1.y, a1.z, a1.w};
        #pragma unroll
        for (int r = 0; r < 8; r++) {
            acc[r][0] += ar[r] * b.x;
            acc[r][1] += ar[r] * b.y;
            acc[r][2] += ar[r] * b.z;
            acc[r][3] += ar[r] * b.w;
        }
    }

    float* outp = g_state + ((size_t)nh * NC + c) * STATE;
    #pragma unroll
    for (int r = 0; r < 8; r++)
        *(float4*)(outp + (d0 + r) * M + m0) =
            make_float4(acc[r][0], acc[r][1], acc[r][2], acc[r][3]);

    if (tid < D) {
        float s = 0.0f;
        #pragma unroll 4
        for (int t = 0; t < T; t++) s += sk[t * D + tid];
        outp[D * M + tid] = s;
    }
}

// ---------------------------------------------------------------------------
// Kernel 2: in-place exclusive prefix scan over chunks, per (n,h).
// ---------------------------------------------------------------------------
constexpr int SCAN_SEG = 8;
constexpr int SEG_LEN  = STATE / SCAN_SEG;   // 520

__global__ __launch_bounds__(256)
void k_scan() {
    const int nh  = blockIdx.x;
    const int seg = blockIdx.y;
    const int e0  = seg * SEG_LEN;
    for (int e = e0 + threadIdx.x; e < e0 + SEG_LEN; e += 256) {
        float acc = 0.0f;
        size_t base = (size_t)nh * NC * STATE + e;
        #pragma unroll 4
        for (int c = 0; c < NC; c++) {
            float t = g_state[base + (size_t)c * STATE];
            g_state[base + (size_t)c * STATE] = acc;
            acc += t;
        }
    }
}

// ---------------------------------------------------------------------------
// Kernel 3: per-chunk output
//   o = phi(q) @ S_prefix + tril(phi(q) phi(k)^T) @ v
//   z = phi(q).ksum_prefix + rowsum(tril(A)) + eps ;  out = o / z
// smem ~67.8KB -> 3 CTAs/SM -> 24 warps resident.
// sA is aliased onto kt (kt dead after phase B; only triangle-active tiles
// of sA are ever read, and only those are written).
// ---------------------------------------------------------------------------
constexpr int QS = 68;    // sq row stride (pad: avoid bank conflicts)
constexpr int TS = 68;    // k-transposed row stride == sA row stride

constexpr int OFF_SQ = 0;                  // [T][QS]
constexpr int OFF_KT = OFF_SQ + T * QS;    // [D][TS]  (phi(k)^T, later reused as sA [T][TS])
constexpr int OFF_SV = OFF_KT + D * TS;    // [T][M]
constexpr int OFF_SS = OFF_SV + T * M;     // [D][M]   (prefix KV state)
constexpr int OFF_KS = OFF_SS + D * M;     // [D]      (prefix ksum) — contiguous after sS
constexpr int SMEM3  = (OFF_KS + D) * 4;   // 67840 B

__global__ __launch_bounds__(256, 3)
void k_output(const float* __restrict__ qin, const float* __restrict__ kin,
              const float* __restrict__ vin, float* __restrict__ out) {
    extern __shared__ float sm[];
    float* sq  = sm + OFF_SQ;
    float* kt  = sm + OFF_KT;
    float* sA  = sm + OFF_KT;   // alias: same storage as kt
    float* sv  = sm + OFF_SV;
    float* sS  = sm + OFF_SS;
    float* sks = sm + OFF_KS;

    const int c  = blockIdx.x;
    const int nh = blockIdx.y;
    const int n  = nh / H, h = nh % H;
    const int l0 = c * T;
    const int tid = threadIdx.x;

    // ---- prefetch exclusive-prefix state into sS/sks via cp.async (16640 B,
    //      contiguous), overlapped with the q/k/v loads and phase B.
    {
        const float* st = g_state + ((size_t)nh * NC + c) * STATE;
        uint32_t sbase = (uint32_t)__cvta_generic_to_shared(sS);
        for (int i = tid; i < STATE / 4; i += 256)
            cp_async16(sbase + i * 16, st + i * 4);
        asm volatile("cp.async.commit_group;\n" ::: "memory");
    }

    // ---- load q (phi), k (phi, transposed), v
    for (int e = tid; e < T * (D / 4); e += 256) {
        int row = e >> 4;
        int c4  = (e & 15) * 4;
        size_t g = ((size_t)(n * L + l0 + row) * H + h) * D + c4;
        float4 qv = *(const float4*)(qin + g);
        qv.x = phi(qv.x); qv.y = phi(qv.y); qv.z = phi(qv.z); qv.w = phi(qv.w);
        *(float4*)(sq + row * QS + c4) = qv;
        float4 kv = *(const float4*)(kin + g);
        kt[(c4 + 0) * TS + row] = phi(kv.x);
        kt[(c4 + 1) * TS + row] = phi(kv.y);
        kt[(c4 + 2) * TS + row] = phi(kv.z);
        kt[(c4 + 3) * TS + row] = phi(kv.w);
        *(float4*)(sv + row * M + c4) = *(const float4*)(vin + g);
    }
    __syncthreads();

    const int rowg = tid >> 4, colg = tid & 15;
    const int i0 = rowg * 4, j0 = colg * 4;
    const bool active = (colg <= rowg);   // tile touches the lower triangle

    // ---- phase B: A = tril(phi(q) @ phi(k)^T), 4x4 register tile per thread
    float a4[4][4];
    #pragma unroll
    for (int r = 0; r < 4; r++)
        #pragma unroll
        for (int j = 0; j < 4; j++) a4[r][j] = 0.0f;

    if (active) {
        #pragma unroll 4
        for (int d = 0; d < D; d++) {
            float4 b = *(float4*)(kt + d * TS + j0);
            float bb[4] = {b.x, b.y, b.z, b.w};
            #pragma unroll
            for (int r = 0; r < 4; r++) {
                float av = sq[(i0 + r) * QS + d];
                #pragma unroll
                for (int j = 0; j < 4; j++) a4[r][j] += av * bb[j];
            }
        }
    }

    // state prefetch must have landed before AC reads sS/sks (after next barrier)
    asm volatile("cp.async.wait_group 0;\n" ::: "memory");
    __syncthreads();   // all kt reads done; safe to overwrite with sA

    if (active) {
        #pragma unroll
        for (int r = 0; r < 4; r++) {
            int i = i0 + r;
            #pragma unroll
            for (int j = 0; j < 4; j++)
                if (j0 + j > i) a4[r][j] = 0.0f;   // causal mask (inclusive diag)
            *(float4*)(sA + i * TS + j0) =
                make_float4(a4[r][0], a4[r][1], a4[r][2], a4[r][3]);
        }
    }
    __syncthreads();

    // ---- phase AC: o = q@S + A@v ; z = q.ksum + rowsum(A) + eps
    const int m0 = colg * 4;
    float acc[4][4];
    float zac[4];
    #pragma unroll
    for (int r = 0; r < 4; r++) {
        zac[r] = EPS;
        acc[r][0] = acc[r][1] = acc[r][2] = acc[r][3] = 0.0f;
    }

    #pragma unroll 4
    for (int d = 0; d < D; d++) {
        float4 s4 = *(float4*)(sS + d * M + m0);
        float kd = sks[d];
        #pragma unroll
        for (int r = 0; r < 4; r++) {
            float av = sq[(i0 + r) * QS + d];
            acc[r][0] += av * s4.x; acc[r][1] += av * s4.y;
            acc[r][2] += av * s4.z; acc[r][3] += av * s4.w;
            zac[r]    += av * kd;
        }
    }
    const int jmax = i0 + 4;   // rows i0..i0+3 only need keys j <= i0+3
    #pragma unroll 4
    for (int j = 0; j < jmax; j++) {
        float4 v4 = *(float4*)(sv + j * M + m0);
        #pragma unroll
        for (int r = 0; r < 4; r++) {
            float av = sA[(i0 + r) * TS + j];   // zero above diagonal
            acc[r][0] += av * v4.x; acc[r][1] += av * v4.y;
            acc[r][2] += av * v4.z; acc[r][3] += av * v4.w;
            zac[r]    += av;
        }
    }
    #pragma unroll
    for (int r = 0; r < 4; r++) {
        float inv = 1.0f / zac[r];
        size_t g = ((size_t)(n * L + l0 + i0 + r) * H + h) * M + m0;
        *(float4*)(out + g) = make_float4(acc[r][0] * inv, acc[r][1] * inv,
                                          acc[r][2] * inv, acc[r][3] * inv);
    }
}

// ---------------------------------------------------------------------------
extern "C" void kernel_launch(void* const* d_in, const int* in_sizes, int n_in,
                              void* d_out, int out_size) {
    const float* q = (const float*)d_in[0];
    const float* k = (const float*)d_in[1];
    const float* v = (const float*)d_in[2];
    float* out = (float*)d_out;

    cudaFuncSetAttribute(k_output, cudaFuncAttributeMaxDynamicSharedMemorySize, SMEM3);

    dim3 grid(NC, NH);
    k_chunksum<<<grid, 128, SMEM1>>>(k, v);
    dim3 sgrid(NH, SCAN_SEG);
    k_scan<<<sgrid, 256>>>();
    k_output<<<grid, 256, SMEM3>>>(q, k, v, out);
}